// round 1
// baseline (speedup 1.0000x reference)
#include <cuda_runtime.h>

#define NL 4
#define TPB 256

__device__ __forceinline__ float fast_tanh(float v) {
    float r;
    asm("tanh.approx.f32 %0, %1;" : "=f"(r) : "f"(v));
    return r;
}

// RX-style apply: U = [[c, -i s], [-i s, c]] acting on (a, b) amplitudes.
__device__ __forceinline__ void apply_rx(float c, float s, float2& a, float2& b) {
    float2 na, nb;
    na.x = c * a.x + s * b.y;
    na.y = c * a.y - s * b.x;
    nb.x = c * b.x + s * a.y;
    nb.y = c * b.y - s * a.x;
    a = na; b = nb;
}

// General complex 2x2 apply: R packed as [r00.re, r00.im, r01.re, r01.im,
//                                         r10.re, r10.im, r11.re, r11.im]
__device__ __forceinline__ void apply_rot(const float* __restrict__ R,
                                          float2& a, float2& b) {
    float2 na, nb;
    na.x = R[0] * a.x - R[1] * a.y + R[2] * b.x - R[3] * b.y;
    na.y = R[0] * a.y + R[1] * a.x + R[2] * b.y + R[3] * b.x;
    nb.x = R[4] * a.x - R[5] * a.y + R[6] * b.x - R[7] * b.y;
    nb.y = R[4] * a.y + R[5] * a.x + R[6] * b.y + R[7] * b.x;
    a = na; b = nb;
}

__global__ __launch_bounds__(TPB) void hybrid_qnn_kernel(
    const float* __restrict__ x,
    const float* __restrict__ w1, const float* __restrict__ b1,
    const float* __restrict__ w2, const float* __restrict__ b2,
    const float* __restrict__ qw,
    const float* __restrict__ pw, const float* __restrict__ pb,
    float* __restrict__ out, int B)
{
    // sP: [0:8) w1, [8:12) b1, [12:20) w2, [20:22) b2, [22:24) post_w, [24] post_b
    __shared__ float sP[25];
    __shared__ float sR[NL][2][8];

    int tid = threadIdx.x;

    // --- cooperative load of tiny classical params ---
    if (tid < 8)        sP[tid] = w1[tid];
    else if (tid < 12)  sP[tid] = b1[tid - 8];
    else if (tid < 20)  sP[tid] = w2[tid - 12];
    else if (tid < 22)  sP[tid] = b2[tid - 20];
    else if (tid < 24)  sP[tid] = pw[tid - 22];
    else if (tid == 24) sP[24]  = pb[0];

    // --- 8 threads (warp 1) each build one Rot matrix (batch-invariant) ---
    if (tid >= 32 && tid < 40) {
        int t = tid - 32;
        int l = t >> 1, w = t & 1;
        const float* q = qw + (l * 2 + w) * 3;
        float phi = q[0], th = q[1], om = q[2];
        float st, ct, sp, cp, sm, cm;
        sincosf(0.5f * th, &st, &ct);
        sincosf(0.5f * (phi + om), &sp, &cp);  // ep = cp - i sp
        sincosf(0.5f * (phi - om), &sm, &cm);  // em = cm - i sm
        float* R = sR[l][w];
        R[0] =  cp * ct;  R[1] = -sp * ct;   // r00 = ep * c
        R[2] = -cm * st;  R[3] = -sm * st;   // r01 = -conj(em) * s
        R[4] =  cm * st;  R[5] = -sm * st;   // r10 = em * s
        R[6] =  cp * ct;  R[7] =  sp * ct;   // r11 = conj(ep) * c
    }
    __syncthreads();

    int i = blockIdx.x * TPB + tid;
    if (i >= B) return;

    float2 xv = reinterpret_cast<const float2*>(x)[i];

    // classical pre-net
    float h0 = fast_tanh(sP[0] * xv.x + sP[1] * xv.y + sP[8]);
    float h1 = fast_tanh(sP[2] * xv.x + sP[3] * xv.y + sP[9]);
    float h2 = fast_tanh(sP[4] * xv.x + sP[5] * xv.y + sP[10]);
    float h3 = fast_tanh(sP[6] * xv.x + sP[7] * xv.y + sP[11]);
    float a0 = fast_tanh(sP[12] * h0 + sP[13] * h1 + sP[14] * h2 + sP[15] * h3 + sP[20]);
    float a1 = fast_tanh(sP[16] * h0 + sP[17] * h1 + sP[18] * h2 + sP[19] * h3 + sP[21]);

    float s0, c0, s1, c1;
    __sincosf(0.5f * a0, &s0, &c0);
    __sincosf(0.5f * a1, &s1, &c1);

    // state[q0][q1], init |00>
    float2 s00 = make_float2(1.f, 0.f);
    float2 s01 = make_float2(0.f, 0.f);
    float2 s10 = make_float2(0.f, 0.f);
    float2 s11 = make_float2(0.f, 0.f);

#pragma unroll
    for (int l = 0; l < NL; l++) {
        // AngleEmbedding: RX(a0) on qubit0 (first index), RX(a1) on qubit1
        apply_rx(c0, s0, s00, s10);
        apply_rx(c0, s0, s01, s11);
        apply_rx(c1, s1, s00, s01);
        apply_rx(c1, s1, s10, s11);
        // Rot on each wire
        apply_rot(sR[l][0], s00, s10);
        apply_rot(sR[l][0], s01, s11);
        apply_rot(sR[l][1], s00, s01);
        apply_rot(sR[l][1], s10, s11);
        // CNOT(0,1): swap s10 <-> s11
        float2 t = s10; s10 = s11; s11 = t;
        // CNOT(1,0): swap s01 <-> s11
        t = s01; s01 = s11; s11 = t;
    }

    float p00 = s00.x * s00.x + s00.y * s00.y;
    float p01 = s01.x * s01.x + s01.y * s01.y;
    float p10 = s10.x * s10.x + s10.y * s10.y;
    float p11 = s11.x * s11.x + s11.y * s11.y;

    float z0 = (p00 + p01) - (p10 + p11);
    float z1 = (p00 + p10) - (p01 + p11);
    float q0 = 0.5f * (z0 + 1.0f);
    float q1 = 0.5f * (z1 + 1.0f);

    float y = q0 * sP[22] + q1 * sP[23] + sP[24];
    out[i] = 1.0f / (1.0f + __expf(-y));
}

extern "C" void kernel_launch(void* const* d_in, const int* in_sizes, int n_in,
                              void* d_out, int out_size) {
    const float* x   = (const float*)d_in[0];
    const float* w1  = (const float*)d_in[1];
    const float* b1  = (const float*)d_in[2];
    const float* w2  = (const float*)d_in[3];
    const float* b2  = (const float*)d_in[4];
    const float* qw  = (const float*)d_in[5];
    const float* pw  = (const float*)d_in[6];
    const float* pb  = (const float*)d_in[7];
    float* out = (float*)d_out;

    int B = in_sizes[0] / 2;
    int grid = (B + TPB - 1) / TPB;
    hybrid_qnn_kernel<<<grid, TPB>>>(x, w1, b1, w2, b2, qw, pw, pb, out, B);
}

// round 2
// speedup vs baseline: 1.0097x; 1.0097x over previous
#include <cuda_runtime.h>

#define NL 4
#define TPB 256

__device__ __forceinline__ float fast_tanh(float v) {
    float r;
    asm("tanh.approx.f32 %0, %1;" : "=f"(r) : "f"(v));
    return r;
}

// RX-style apply: U = [[c, -i s], [-i s, c]] acting on (a, b) amplitudes.
__device__ __forceinline__ void apply_rx(float c, float s, float2& a, float2& b) {
    float2 na, nb;
    na.x = c * a.x + s * b.y;
    na.y = c * a.y - s * b.x;
    nb.x = c * b.x + s * a.y;
    nb.y = c * b.y - s * a.x;
    a = na; b = nb;
}

// General complex 2x2 apply: R packed as [r00.re, r00.im, r01.re, r01.im,
//                                         r10.re, r10.im, r11.re, r11.im]
__device__ __forceinline__ void apply_rot(const float* __restrict__ R,
                                          float2& a, float2& b) {
    float2 na, nb;
    na.x = R[0] * a.x - R[1] * a.y + R[2] * b.x - R[3] * b.y;
    na.y = R[0] * a.y + R[1] * a.x + R[2] * b.y + R[3] * b.x;
    nb.x = R[4] * a.x - R[5] * a.y + R[6] * b.x - R[7] * b.y;
    nb.y = R[4] * a.y + R[5] * a.x + R[6] * b.y + R[7] * b.x;
    a = na; b = nb;
}

__global__ __launch_bounds__(TPB) void hybrid_qnn_kernel(
    const float* __restrict__ x,
    const float* __restrict__ w1, const float* __restrict__ b1,
    const float* __restrict__ w2, const float* __restrict__ b2,
    const float* __restrict__ qw,
    const float* __restrict__ pw, const float* __restrict__ pb,
    float* __restrict__ out, int B)
{
    // sP: [0:8) w1, [8:12) b1, [12:20) w2, [20:22) b2, [22:24) post_w, [24] post_b
    __shared__ float sP[25];
    __shared__ float sR[NL][2][8];

    int tid = threadIdx.x;

    // --- cooperative load of tiny classical params ---
    if (tid < 8)        sP[tid] = w1[tid];
    else if (tid < 12)  sP[tid] = b1[tid - 8];
    else if (tid < 20)  sP[tid] = w2[tid - 12];
    else if (tid < 22)  sP[tid] = b2[tid - 20];
    else if (tid < 24)  sP[tid] = pw[tid - 22];
    else if (tid == 24) sP[24]  = pb[0];

    // --- 8 threads (warp 1) each build one Rot matrix (batch-invariant) ---
    if (tid >= 32 && tid < 40) {
        int t = tid - 32;
        int l = t >> 1, w = t & 1;
        const float* q = qw + (l * 2 + w) * 3;
        float phi = q[0], th = q[1], om = q[2];
        float st, ct, sp, cp, sm, cm;
        sincosf(0.5f * th, &st, &ct);
        sincosf(0.5f * (phi + om), &sp, &cp);  // ep = cp - i sp
        sincosf(0.5f * (phi - om), &sm, &cm);  // em = cm - i sm
        float* R = sR[l][w];
        R[0] =  cp * ct;  R[1] = -sp * ct;   // r00 = ep * c
        R[2] = -cm * st;  R[3] = -sm * st;   // r01 = -conj(em) * s
        R[4] =  cm * st;  R[5] = -sm * st;   // r10 = em * s
        R[6] =  cp * ct;  R[7] =  sp * ct;   // r11 = conj(ep) * c
    }
    __syncthreads();

    int i = blockIdx.x * TPB + tid;
    if (i >= B) return;

    float2 xv = reinterpret_cast<const float2*>(x)[i];

    // classical pre-net
    float h0 = fast_tanh(sP[0] * xv.x + sP[1] * xv.y + sP[8]);
    float h1 = fast_tanh(sP[2] * xv.x + sP[3] * xv.y + sP[9]);
    float h2 = fast_tanh(sP[4] * xv.x + sP[5] * xv.y + sP[10]);
    float h3 = fast_tanh(sP[6] * xv.x + sP[7] * xv.y + sP[11]);
    float a0 = fast_tanh(sP[12] * h0 + sP[13] * h1 + sP[14] * h2 + sP[15] * h3 + sP[20]);
    float a1 = fast_tanh(sP[16] * h0 + sP[17] * h1 + sP[18] * h2 + sP[19] * h3 + sP[21]);

    float s0, c0, s1, c1;
    __sincosf(0.5f * a0, &s0, &c0);
    __sincosf(0.5f * a1, &s1, &c1);

    // state[q0][q1], init |00>
    float2 s00 = make_float2(1.f, 0.f);
    float2 s01 = make_float2(0.f, 0.f);
    float2 s10 = make_float2(0.f, 0.f);
    float2 s11 = make_float2(0.f, 0.f);

#pragma unroll
    for (int l = 0; l < NL; l++) {
        // AngleEmbedding: RX(a0) on qubit0 (first index), RX(a1) on qubit1
        apply_rx(c0, s0, s00, s10);
        apply_rx(c0, s0, s01, s11);
        apply_rx(c1, s1, s00, s01);
        apply_rx(c1, s1, s10, s11);
        // Rot on each wire
        apply_rot(sR[l][0], s00, s10);
        apply_rot(sR[l][0], s01, s11);
        apply_rot(sR[l][1], s00, s01);
        apply_rot(sR[l][1], s10, s11);
        // CNOT(0,1): swap s10 <-> s11
        float2 t = s10; s10 = s11; s11 = t;
        // CNOT(1,0): swap s01 <-> s11
        t = s01; s01 = s11; s11 = t;
    }

    float p00 = s00.x * s00.x + s00.y * s00.y;
    float p01 = s01.x * s01.x + s01.y * s01.y;
    float p10 = s10.x * s10.x + s10.y * s10.y;
    float p11 = s11.x * s11.x + s11.y * s11.y;

    float z0 = (p00 + p01) - (p10 + p11);
    float z1 = (p00 + p10) - (p01 + p11);
    float q0 = 0.5f * (z0 + 1.0f);
    float q1 = 0.5f * (z1 + 1.0f);

    float y = q0 * sP[22] + q1 * sP[23] + sP[24];
    out[i] = 1.0f / (1.0f + __expf(-y));
}

extern "C" void kernel_launch(void* const* d_in, const int* in_sizes, int n_in,
                              void* d_out, int out_size) {
    const float* x   = (const float*)d_in[0];
    const float* w1  = (const float*)d_in[1];
    const float* b1  = (const float*)d_in[2];
    const float* w2  = (const float*)d_in[3];
    const float* b2  = (const float*)d_in[4];
    const float* qw  = (const float*)d_in[5];
    const float* pw  = (const float*)d_in[6];
    const float* pb  = (const float*)d_in[7];
    float* out = (float*)d_out;

    int B = in_sizes[0] / 2;
    int grid = (B + TPB - 1) / TPB;
    hybrid_qnn_kernel<<<grid, TPB>>>(x, w1, b1, w2, b2, qw, pw, pb, out, B);
}

// round 3
// speedup vs baseline: 1.1099x; 1.0992x over previous
#include <cuda_runtime.h>

#define NL 4
#define TPB 256

typedef unsigned long long u64;

// ---- packed 2x f32 (Blackwell f32x2 pipe) ----
struct p2 { u64 v; };

__device__ __forceinline__ p2 mk2(float lo, float hi) {
    p2 r; asm("mov.b64 %0, {%1,%2};" : "=l"(r.v) : "f"(lo), "f"(hi)); return r;
}
__device__ __forceinline__ void un2(p2 a, float& lo, float& hi) {
    asm("mov.b64 {%0,%1}, %2;" : "=f"(lo), "=f"(hi) : "l"(a.v));
}
__device__ __forceinline__ p2 fma2(p2 a, p2 b, p2 c) {
    p2 r; asm("fma.rn.f32x2 %0, %1, %2, %3;" : "=l"(r.v) : "l"(a.v), "l"(b.v), "l"(c.v)); return r;
}
__device__ __forceinline__ p2 mul2(p2 a, p2 b) {
    p2 r; asm("mul.rn.f32x2 %0, %1, %2;" : "=l"(r.v) : "l"(a.v), "l"(b.v)); return r;
}
__device__ __forceinline__ p2 add2(p2 a, p2 b) {
    p2 r; asm("add.rn.f32x2 %0, %1, %2;" : "=l"(r.v) : "l"(a.v), "l"(b.v)); return r;
}
__device__ __forceinline__ p2 neg2(p2 a) { p2 r; r.v = a.v ^ 0x8000000080000000ULL; return r; }

__device__ __forceinline__ float fast_tanh(float v) {
    float r; asm("tanh.approx.f32 %0, %1;" : "=f"(r) : "f"(v)); return r;
}

// RX: na = c*a + s*(i-swapped b); packed across 2 samples, ns = -s.
__device__ __forceinline__ void apply_rx(p2 c, p2 s, p2 ns,
                                         p2& ax, p2& ay, p2& bx, p2& by) {
    p2 nax = fma2(c, ax, mul2(s,  by));
    p2 nay = fma2(c, ay, mul2(ns, bx));
    p2 nbx = fma2(c, bx, mul2(s,  ay));
    p2 nby = fma2(c, by, mul2(ns, ax));
    ax = nax; ay = nay; bx = nbx; by = nby;
}

// SU(2) rot: R = [[a, b], [-conj(b), conj(a)]], 7 pre-negated packed scalars.
__device__ __forceinline__ void apply_rot(p2 ar, p2 ai, p2 nai,
                                          p2 br, p2 nbr, p2 bi, p2 nbi,
                                          p2& ax, p2& ay, p2& bx, p2& by) {
    p2 nax = fma2(nbi, by, fma2(br,  bx, fma2(nai, ay, mul2(ar,  ax))));
    p2 nay = fma2(bi,  bx, fma2(br,  by, fma2(ai,  ax, mul2(ar,  ay))));
    p2 nbx = fma2(ai,  by, fma2(ar,  bx, fma2(nbi, ay, mul2(nbr, ax))));
    p2 nby = fma2(nai, bx, fma2(ar,  by, fma2(bi,  ax, mul2(nbr, ay))));
    ax = nax; ay = nay; bx = nbx; by = nby;
}

__global__ __launch_bounds__(TPB) void hybrid_qnn_kernel(
    const float4* __restrict__ x4,
    const float* __restrict__ w1, const float* __restrict__ b1,
    const float* __restrict__ w2, const float* __restrict__ b2,
    const float* __restrict__ qw,
    const float* __restrict__ pw, const float* __restrict__ pb,
    float2* __restrict__ out2, int B2)
{
    // sP: duplicated packed params. [0:8) w1, [8:12) b1, [12:20) w2,
    //     [20:22) b2, [22:24) post_w, [24] post_b
    __shared__ float2 sP[25];
    // sR[m][k]: matrix m = l*2+wire, k: 0=ar 1=ai 2=-ai 3=br 4=-br 5=bi 6=-bi
    __shared__ float2 sR[NL * 2][8];

    int tid = threadIdx.x;

    if (tid < 25) {
        float v;
        if (tid < 8)       v = w1[tid];
        else if (tid < 12) v = b1[tid - 8];
        else if (tid < 20) v = w2[tid - 12];
        else if (tid < 22) v = b2[tid - 20];
        else if (tid < 24) v = pw[tid - 22];
        else               v = pb[0];
        sP[tid] = make_float2(v, v);
    }

    // 8 threads of warp 1 each build one SU(2) matrix (batch-invariant)
    if (tid >= 32 && tid < 40) {
        int m = tid - 32;
        const float* q = qw + m * 3;
        float phi = q[0], th = q[1], om = q[2];
        float st, ct, sp, cp, sm, cm;
        sincosf(0.5f * th, &st, &ct);
        sincosf(0.5f * (phi + om), &sp, &cp);
        sincosf(0.5f * (phi - om), &sm, &cm);
        float ar =  cp * ct, ai = -sp * ct;   // r00 = ep * c
        float br = -cm * st, bi = -sm * st;   // r01 = -conj(em) * s
        sR[m][0] = make_float2(ar, ar);
        sR[m][1] = make_float2(ai, ai);
        sR[m][2] = make_float2(-ai, -ai);
        sR[m][3] = make_float2(br, br);
        sR[m][4] = make_float2(-br, -br);
        sR[m][5] = make_float2(bi, bi);
        sR[m][6] = make_float2(-bi, -bi);
    }
    __syncthreads();

    int i = blockIdx.x * TPB + tid;
    if (i >= B2) return;

    const p2* P = reinterpret_cast<const p2*>(sP);

    // two samples: 2i and 2i+1
    float4 xv = x4[i];
    p2 X0 = mk2(xv.x, xv.z);
    p2 X1 = mk2(xv.y, xv.w);

    // ---- pre-net (packed FMAs, scalar tanh) ----
    float lo, hi;
    p2 h[4];
#pragma unroll
    for (int j = 0; j < 4; j++) {
        p2 t = fma2(P[2*j], X0, fma2(P[2*j+1], X1, P[8+j]));
        un2(t, lo, hi);
        h[j] = mk2(fast_tanh(lo), fast_tanh(hi));
    }
    p2 t0 = fma2(P[12], h[0], fma2(P[13], h[1], fma2(P[14], h[2], fma2(P[15], h[3], P[20]))));
    p2 t1 = fma2(P[16], h[0], fma2(P[17], h[1], fma2(P[18], h[2], fma2(P[19], h[3], P[21]))));

    float a0l, a0h, a1l, a1h;
    un2(t0, a0l, a0h); un2(t1, a1l, a1h);
    a0l = fast_tanh(a0l); a0h = fast_tanh(a0h);
    a1l = fast_tanh(a1l); a1h = fast_tanh(a1h);

    float sl, cl, sh, ch;
    __sincosf(0.5f * a0l, &sl, &cl); __sincosf(0.5f * a0h, &sh, &ch);
    p2 c0 = mk2(cl, ch), s0 = mk2(sl, sh);
    __sincosf(0.5f * a1l, &sl, &cl); __sincosf(0.5f * a1h, &sh, &ch);
    p2 c1 = mk2(cl, ch), s1 = mk2(sl, sh);
    p2 ns0 = neg2(s0), ns1 = neg2(s1);

    // ---- quantum state: amplitudes s[q0][q1], re/im packed across 2 samples ----
    p2 one = mk2(1.f, 1.f), zero; zero.v = 0ULL;
    p2 s00x = one,  s00y = zero;
    p2 s01x = zero, s01y = zero;
    p2 s10x = zero, s10y = zero;
    p2 s11x = zero, s11y = zero;

#pragma unroll
    for (int l = 0; l < NL; l++) {
        // AngleEmbedding: RX(a0) on qubit0, RX(a1) on qubit1
        apply_rx(c0, s0, ns0, s00x, s00y, s10x, s10y);
        apply_rx(c0, s0, ns0, s01x, s01y, s11x, s11y);
        apply_rx(c1, s1, ns1, s00x, s00y, s01x, s01y);
        apply_rx(c1, s1, ns1, s10x, s10y, s11x, s11y);
        // Rot wire 0
        {
            const p2* M = reinterpret_cast<const p2*>(sR[l * 2 + 0]);
            p2 ar = M[0], ai = M[1], nai = M[2], br = M[3], nbr = M[4], bi = M[5], nbi = M[6];
            apply_rot(ar, ai, nai, br, nbr, bi, nbi, s00x, s00y, s10x, s10y);
            apply_rot(ar, ai, nai, br, nbr, bi, nbi, s01x, s01y, s11x, s11y);
        }
        // Rot wire 1
        {
            const p2* M = reinterpret_cast<const p2*>(sR[l * 2 + 1]);
            p2 ar = M[0], ai = M[1], nai = M[2], br = M[3], nbr = M[4], bi = M[5], nbi = M[6];
            apply_rot(ar, ai, nai, br, nbr, bi, nbi, s00x, s00y, s01x, s01y);
            apply_rot(ar, ai, nai, br, nbr, bi, nbi, s10x, s10y, s11x, s11y);
        }
        // CNOT(0,1): swap s10 <-> s11 ; CNOT(1,0): swap s01 <-> s11
        p2 tx = s10x, ty = s10y; s10x = s11x; s10y = s11y; s11x = tx; s11y = ty;
        tx = s01x; ty = s01y; s01x = s11x; s01y = s11y; s11x = tx; s11y = ty;
    }

    // ---- measurement; unitarity => q0 = p00+p01, q1 = p00+p10 ----
    p2 m00 = fma2(s00y, s00y, mul2(s00x, s00x));
    p2 q0 = fma2(s01y, s01y, fma2(s01x, s01x, m00));
    p2 q1 = fma2(s10y, s10y, fma2(s10x, s10x, m00));

    p2 y = fma2(P[22], q0, fma2(P[23], q1, P[24]));
    float yl, yh;
    un2(y, yl, yh);
    // sigmoid(y) = 0.5*tanh(y/2) + 0.5
    float o0 = fmaf(0.5f, fast_tanh(0.5f * yl), 0.5f);
    float o1 = fmaf(0.5f, fast_tanh(0.5f * yh), 0.5f);
    out2[i] = make_float2(o0, o1);
}

extern "C" void kernel_launch(void* const* d_in, const int* in_sizes, int n_in,
                              void* d_out, int out_size) {
    const float4* x  = (const float4*)d_in[0];
    const float* w1  = (const float*)d_in[1];
    const float* b1  = (const float*)d_in[2];
    const float* w2  = (const float*)d_in[3];
    const float* b2  = (const float*)d_in[4];
    const float* qw  = (const float*)d_in[5];
    const float* pw  = (const float*)d_in[6];
    const float* pb  = (const float*)d_in[7];
    float2* out = (float2*)d_out;

    int B2 = in_sizes[0] / 4;  // two samples per thread
    int grid = (B2 + TPB - 1) / TPB;
    hybrid_qnn_kernel<<<grid, TPB>>>(x, w1, b1, w2, b2, qw, pw, pb, out, B2);
}